// round 16
// baseline (speedup 1.0000x reference)
#include <cuda_runtime.h>
#include <cuda_fp16.h>
#include <cstdint>

// ---------------------------------------------------------------------------
// Round 15: BM=64 TC tiles (64-thr CTAs, 2 warps @ 64x64), H GEMM split-K
// removed with fused epilogue; Z GEMM split-K=2 + fp16 reduce.
//   A (relu(attn)) -> fp16 plane;  B (P/Q) -> fp16 plane scaled 2^14.
//   Z fp16 (L2-resident); 16-lane decode.
// ---------------------------------------------------------------------------

static constexpr int N_NODES = 8192;
static constexpr int E_DIM_C = 256;
static constexpr int HID_C   = 256;
static constexpr int OUT_C   = 128;
static constexpr float B_SCALE     = 16384.0f;       // 2^14
static constexpr float B_INV_SCALE = 1.0f / 16384.0f;

__device__ float   g_degp[128 * N_NODES];
__device__ float   g_dis [N_NODES];
__device__ __half  g_Af  [(size_t)N_NODES * N_NODES];   // 128 MB fp16 relu(attn)
__device__ __half  g_Bf  [N_NODES * HID_C];             // P/Q (scaled fp16)
__device__ float   g_H   [N_NODES * HID_C];
__device__ __half  g_Zh  [N_NODES * OUT_C];             // 2 MB fp16 Z
__device__ float   g_part[2 * N_NODES * OUT_C];         // Z split-K partials

// ---------------------------------------------------------------------------
__global__ void convert_deg_kernel(const float* __restrict__ attn)
{
    int c4 = blockIdx.x * blockDim.x + threadIdx.x;
    int r0 = blockIdx.y * 64;
    float4 s = make_float4(0.f, 0.f, 0.f, 0.f);
    const float4* a = reinterpret_cast<const float4*>(attn);
    #pragma unroll 4
    for (int r = 0; r < 64; ++r) {
        size_t row = r0 + r;
        float4 v = a[row * (N_NODES / 4) + c4];
        v.x = fmaxf(v.x, 0.f); v.y = fmaxf(v.y, 0.f);
        v.z = fmaxf(v.z, 0.f); v.w = fmaxf(v.w, 0.f);
        s.x += v.x; s.y += v.y; s.z += v.z; s.w += v.w;
        __half2 h0 = __floats2half2_rn(v.x, v.y);
        __half2 h1 = __floats2half2_rn(v.z, v.w);
        uint2 packed;
        packed.x = *reinterpret_cast<uint32_t*>(&h0);
        packed.y = *reinterpret_cast<uint32_t*>(&h1);
        reinterpret_cast<uint2*>(g_Af)[(row * N_NODES) / 4 + c4] = packed;
    }
    reinterpret_cast<float4*>(g_degp)[blockIdx.y * (N_NODES / 4) + c4] = s;
}

__global__ void dis_kernel()
{
    int col = blockIdx.x * blockDim.x + threadIdx.x;
    float s = 0.f;
    #pragma unroll
    for (int r = 0; r < 128; ++r) s += g_degp[(size_t)r * N_NODES + col];
    g_dis[col] = (s > 0.f) ? rsqrtf(s) : 0.f;
}

// ---------------------------------------------------------------------------
__device__ __forceinline__ void ldsm_x4_t(uint32_t& r0, uint32_t& r1,
                                          uint32_t& r2, uint32_t& r3, uint32_t addr)
{
    asm volatile("ldmatrix.sync.aligned.m8n8.x4.trans.shared.b16 {%0,%1,%2,%3}, [%4];"
                 : "=r"(r0), "=r"(r1), "=r"(r2), "=r"(r3) : "r"(addr));
}

__device__ __forceinline__ void mma16816h(float* d, const uint32_t* a, const uint32_t* b)
{
    asm volatile("mma.sync.aligned.m16n8k16.row.col.f32.f16.f16.f32 "
                 "{%0,%1,%2,%3}, {%4,%5,%6,%7}, {%8,%9}, {%0,%1,%2,%3};"
                 : "+f"(d[0]), "+f"(d[1]), "+f"(d[2]), "+f"(d[3])
                 : "r"(a[0]), "r"(a[1]), "r"(a[2]), "r"(a[3]), "r"(b[0]), "r"(b[1]));
}

__device__ __forceinline__ void cpasync16(uint32_t smem, const void* gmem)
{
    asm volatile("cp.async.cg.shared.global [%0], [%1], 16;" :: "r"(smem), "l"(gmem));
}

// ---------------------------------------------------------------------------
// TC GEMM, BM=64, BN=128, BK=32, 64 threads (2 warps, warp tile 64x64 in N).
//   Af: [K, M] fp16, Bf: [K, Ntot] fp16 (pre-scaled 2^14). 3-stage cp.async.
//   EPI_H: fused epilogue -> H = relu(dis*val/2^14 + bias) fp32, no split-K.
//   !EPI_H: raw partial at blockIdx.z offset (Z path, split-K).
// ---------------------------------------------------------------------------
template<int SPLITK, bool EPI_H>
__global__ __launch_bounds__(64, 4)
void tc_gemm(const __half* __restrict__ Afg,
             const __half* __restrict__ Bfg,
             float* __restrict__ C,
             const float* __restrict__ bias,
             int M, int Ntot, int K)
{
    constexpr int BM = 64, BN = 128, BK = 32;
    constexpr int AP = 72;                        // BM + 8
    constexpr int BP = BN + 8;                    // 136
    constexpr int ASTG = BK * AP;
    constexpr int BSTG = BK * BP;
    constexpr int NSTAGE = 3;
    constexpr int NT = 64;

    extern __shared__ __half smheap[];
    auto planeA = [&](int s) { return smheap + s * (ASTG + BSTG); };
    auto planeB = [&](int s) { return smheap + s * (ASTG + BSTG) + ASTG; };

    const int tid  = threadIdx.x;
    const int lane = tid & 31;
    const int wid  = tid >> 5;
    const int wn   = wid * 64;                    // warp n offset (0 / 64)
    const int m0   = blockIdx.y * BM;
    const int n0   = blockIdx.x * BN;
    const int Ksp  = K / SPLITK;
    const int kB   = blockIdx.z * Ksp;
    const int KT   = Ksp / BK;

    float acc[4][8][4];
    #pragma unroll
    for (int i = 0; i < 4; ++i)
        #pragma unroll
        for (int j = 0; j < 8; ++j)
            #pragma unroll
            for (int q = 0; q < 4; ++q) acc[i][j][q] = 0.f;

    auto issue = [&](int kt, int s) {
        int kg = kB + kt * BK;
        uint32_t ab = (uint32_t)__cvta_generic_to_shared(planeA(s));
        uint32_t bb = (uint32_t)__cvta_generic_to_shared(planeB(s));
        #pragma unroll
        for (int v = 0; v < 4; ++v) {             // A: 32 rows x 8 chunks
            int idx = tid + v * NT;
            int row = idx >> 3;
            int c16 = idx & 7;
            cpasync16(ab + row * (AP * 2) + c16 * 16,
                      Afg + (size_t)(kg + row) * M + m0 + c16 * 8);
        }
        #pragma unroll
        for (int v = 0; v < 8; ++v) {             // B: 32 rows x 16 chunks
            int idx = tid + v * NT;
            int row = idx >> 4;
            int cc  = idx & 15;
            cpasync16(bb + row * (BP * 2) + cc * 16,
                      Bfg + (size_t)(kg + row) * Ntot + n0 + cc * 8);
        }
        asm volatile("cp.async.commit_group;");
    };

    const int aRow = (lane & 7) + ((lane >> 4) & 1) * 8;
    const int aCol = ((lane >> 3) & 1) * 8;       // wm = 0 (both warps same rows)
    const int bRow = (lane & 7) + ((lane >> 3) & 1) * 8;
    const int bCol = wn + ((lane >> 4) & 1) * 8;

    auto compute = [&](int s) {
        uint32_t ab = (uint32_t)__cvta_generic_to_shared(planeA(s));
        uint32_t bb = (uint32_t)__cvta_generic_to_shared(planeB(s));
        #pragma unroll
        for (int k16 = 0; k16 < 2; ++k16) {
            int k0 = k16 * 16;
            uint32_t bf[8][2];
            #pragma unroll
            for (int p = 0; p < 4; ++p) {
                uint32_t off = ((k0 + bRow) * BP + bCol + p * 16) * 2;
                uint32_t r0, r1, r2, r3;
                ldsm_x4_t(r0, r1, r2, r3, bb + off);
                bf[2 * p][0] = r0; bf[2 * p][1] = r1;
                bf[2 * p + 1][0] = r2; bf[2 * p + 1][1] = r3;
            }
            #pragma unroll
            for (int mi = 0; mi < 4; ++mi) {
                uint32_t af[4];
                uint32_t off = ((k0 + aRow) * AP + aCol + mi * 16) * 2;
                ldsm_x4_t(af[0], af[1], af[2], af[3], ab + off);
                #pragma unroll
                for (int ni = 0; ni < 8; ++ni)
                    mma16816h(acc[mi][ni], af, bf[ni]);
            }
        }
    };

    issue(0, 0);
    if (KT > 1) issue(1, 1);
    if (KT > 2) issue(2, 2);

    for (int kt = 0; kt < KT; ++kt) {
        asm volatile("cp.async.wait_group %0;" :: "n"(NSTAGE - 2));
        __syncthreads();
        compute(kt % NSTAGE);
        __syncthreads();
        if (kt + NSTAGE < KT) {
            issue(kt + NSTAGE, kt % NSTAGE);
        } else if (kt + 1 < KT) {
            asm volatile("cp.async.commit_group;");
        }
    }

    const int rB = m0 + (lane >> 2);
    const int cB = n0 + wn + (lane & 3) * 2;
    if (EPI_H) {
        #pragma unroll
        for (int mi = 0; mi < 4; ++mi) {
            int r0r = rB + mi * 16;
            float sc0 = g_dis[r0r]     * B_INV_SCALE;
            float sc1 = g_dis[r0r + 8] * B_INV_SCALE;
            #pragma unroll
            for (int ni = 0; ni < 8; ++ni) {
                int c = cB + ni * 8;
                float b0 = bias[c], b1 = bias[c + 1];
                float2 lo, hi;
                lo.x = fmaxf(acc[mi][ni][0] * sc0 + b0, 0.f);
                lo.y = fmaxf(acc[mi][ni][1] * sc0 + b1, 0.f);
                hi.x = fmaxf(acc[mi][ni][2] * sc1 + b0, 0.f);
                hi.y = fmaxf(acc[mi][ni][3] * sc1 + b1, 0.f);
                *reinterpret_cast<float2*>(C + (size_t)r0r * Ntot + c) = lo;
                *reinterpret_cast<float2*>(C + (size_t)(r0r + 8) * Ntot + c) = hi;
            }
        }
    } else {
        float* Cp = C + (size_t)blockIdx.z * M * Ntot;
        #pragma unroll
        for (int mi = 0; mi < 4; ++mi)
            #pragma unroll
            for (int ni = 0; ni < 8; ++ni) {
                int r = rB + mi * 16;
                int c = cB + ni * 8;
                *reinterpret_cast<float2*>(Cp + (size_t)r * Ntot + c) =
                    make_float2(acc[mi][ni][0], acc[mi][ni][1]);
                *reinterpret_cast<float2*>(Cp + (size_t)(r + 8) * Ntot + c) =
                    make_float2(acc[mi][ni][2], acc[mi][ni][3]);
            }
    }
}

// ---------------------------------------------------------------------------
// Z split-K reduce + epilogue -> fp16 Z.
// ---------------------------------------------------------------------------
__global__ void reduce_epi_z_kernel(const float* __restrict__ part,
                                    const float* __restrict__ bias)
{
    int i4 = blockIdx.x * blockDim.x + threadIdx.x;
    constexpr int N = OUT_C;
    constexpr int MN4 = N_NODES * N / 4;
    if (i4 >= MN4) return;
    const float4* p = reinterpret_cast<const float4*>(part);
    float4 s = p[i4];
    float4 v = p[i4 + (size_t)MN4];
    s.x += v.x; s.y += v.y; s.z += v.z; s.w += v.w;
    int row = (i4 * 4) / N;
    int col = (i4 * 4) % N;
    float sc = g_dis[row] * B_INV_SCALE;
    float4 bb = *reinterpret_cast<const float4*>(bias + col);
    __half2 h0 = __floats2half2_rn(s.x * sc + bb.x, s.y * sc + bb.y);
    __half2 h1 = __floats2half2_rn(s.z * sc + bb.z, s.w * sc + bb.w);
    uint2 packed;
    packed.x = *reinterpret_cast<uint32_t*>(&h0);
    packed.y = *reinterpret_cast<uint32_t*>(&h1);
    reinterpret_cast<uint2*>(g_Zh)[i4] = packed;
}

// ---------------------------------------------------------------------------
// SIMT fp32 GEMM; epilogue writes one scaled fp16 plane.
// ---------------------------------------------------------------------------
template<int BM, int BN, int BK, int TM, int TN, bool GATHER_A>
__global__ __launch_bounds__((BM / TM) * (BN / TN))
void simt_gemm(const float* __restrict__ A, int lda,
               const float* __restrict__ B,
               __half* __restrict__ Cf,
               const float* __restrict__ rowScale,
               const int* __restrict__ gatherIdx,
               int M, int N, int K)
{
    constexpr int NT   = (BM / TM) * (BN / TN);
    constexpr int APAD = 4;
    constexpr int AV   = (BM * BK) / (4 * NT);
    constexpr int BV   = (BK * BN) / (4 * NT);

    __shared__ float As[BK][BM + APAD];
    __shared__ float Bs[BK][BN];

    const int tid = threadIdx.x;
    const int tx  = tid % (BN / TN);
    const int ty  = tid / (BN / TN);
    const int m0  = blockIdx.y * BM;
    const int n0  = blockIdx.x * BN;

    float4 areg[AV], breg[BV];
    float acc[TM][TN];
    #pragma unroll
    for (int i = 0; i < TM; ++i)
        #pragma unroll
        for (int j = 0; j < TN; ++j) acc[i][j] = 0.f;

    auto loadA = [&](int k0) {
        #pragma unroll
        for (int v = 0; v < AV; ++v) {
            int idx = tid + v * NT;
            int m  = idx / (BK / 4);
            int kq = idx % (BK / 4);
            int row = GATHER_A ? gatherIdx[m0 + m] : (m0 + m);
            areg[v] = *reinterpret_cast<const float4*>(A + (size_t)row * lda + (k0 + kq * 4));
        }
    };
    auto storeA = [&]() {
        #pragma unroll
        for (int v = 0; v < AV; ++v) {
            int idx = tid + v * NT;
            int m  = idx / (BK / 4);
            int kq = idx % (BK / 4);
            As[kq * 4 + 0][m] = areg[v].x;
            As[kq * 4 + 1][m] = areg[v].y;
            As[kq * 4 + 2][m] = areg[v].z;
            As[kq * 4 + 3][m] = areg[v].w;
        }
    };
    auto loadB = [&](int k0) {
        #pragma unroll
        for (int v = 0; v < BV; ++v) {
            int idx = tid + v * NT;
            int k  = idx / (BN / 4);
            int n4 = idx % (BN / 4);
            breg[v] = *reinterpret_cast<const float4*>(B + (size_t)(k0 + k) * N + (n0 + n4 * 4));
        }
    };
    auto storeB = [&]() {
        #pragma unroll
        for (int v = 0; v < BV; ++v) {
            int idx = tid + v * NT;
            int k  = idx / (BN / 4);
            int n4 = idx % (BN / 4);
            *reinterpret_cast<float4*>(&Bs[k][n4 * 4]) = breg[v];
        }
    };

    loadA(0); loadB(0);
    storeA(); storeB();
    __syncthreads();

    const int KT = K / BK;
    for (int kt = 0; kt < KT; ++kt) {
        if (kt + 1 < KT) { loadA((kt + 1) * BK); loadB((kt + 1) * BK); }
        #pragma unroll
        for (int kk = 0; kk < BK; ++kk) {
            float a[TM], b[TN];
            #pragma unroll
            for (int i = 0; i < TM; i += 4) {
                float4 t = *reinterpret_cast<const float4*>(&As[kk][ty * TM + i]);
                a[i] = t.x; a[i + 1] = t.y; a[i + 2] = t.z; a[i + 3] = t.w;
            }
            #pragma unroll
            for (int j = 0; j < TN; j += 4) {
                float4 t = *reinterpret_cast<const float4*>(&Bs[kk][tx * TN + j]);
                b[j] = t.x; b[j + 1] = t.y; b[j + 2] = t.z; b[j + 3] = t.w;
            }
            #pragma unroll
            for (int i = 0; i < TM; ++i)
                #pragma unroll
                for (int j = 0; j < TN; ++j)
                    acc[i][j] = fmaf(a[i], b[j], acc[i][j]);
        }
        if (kt + 1 < KT) {
            __syncthreads();
            storeA(); storeB();
            __syncthreads();
        }
    }

    #pragma unroll
    for (int i = 0; i < TM; ++i) {
        int row = m0 + ty * TM + i;
        float sc = rowScale[row] * B_SCALE;
        #pragma unroll
        for (int j = 0; j < TN; j += 4) {
            int col = n0 + tx * TN + j;
            __half h[4];
            h[0] = __float2half_rn(acc[i][j + 0] * sc);
            h[1] = __float2half_rn(acc[i][j + 1] * sc);
            h[2] = __float2half_rn(acc[i][j + 2] * sc);
            h[3] = __float2half_rn(acc[i][j + 3] * sc);
            reinterpret_cast<uint2*>(Cf)[((size_t)row * N + col) / 4] =
                *reinterpret_cast<uint2*>(h);
        }
    }
}

// ---------------------------------------------------------------------------
// decode: 16 lanes per edge, uint4 loads of fp16 Z.
// ---------------------------------------------------------------------------
__global__ __launch_bounds__(256)
void decode_kernel(const int* __restrict__ eli,
                   float* __restrict__ out, int nPred)
{
    int g = blockIdx.x * blockDim.x + threadIdx.x;
    int e = g >> 4;
    int l16 = threadIdx.x & 15;
    if (e >= nPred) return;
    int s = __ldg(eli + e);
    int d = __ldg(eli + nPred + e);
    const uint4* zs = reinterpret_cast<const uint4*>(g_Zh + (size_t)s * OUT_C);
    const uint4* zd = reinterpret_cast<const uint4*>(g_Zh + (size_t)d * OUT_C);
    uint4 ar = __ldg(zs + l16);
    uint4 br = __ldg(zd + l16);
    float dot = 0.f;
    const uint32_t* au = &ar.x;
    const uint32_t* bu = &br.x;
    #pragma unroll
    for (int q = 0; q < 4; ++q) {
        __half2 ah = *reinterpret_cast<const __half2*>(&au[q]);
        __half2 bh = *reinterpret_cast<const __half2*>(&bu[q]);
        float2 af = __half22float2(ah);
        float2 bf = __half22float2(bh);
        dot += af.x * bf.x + af.y * bf.y;
    }
    #pragma unroll
    for (int o = 8; o; o >>= 1) dot += __shfl_xor_sync(0xffffffffu, dot, o);
    if (l16 == 0) out[e] = dot;
}

// ---------------------------------------------------------------------------
extern "C" void kernel_launch(void* const* d_in, const int* in_sizes, int n_in,
                              void* d_out, int out_size)
{
    const int*   nodeIdx = (const int*)  d_in[0];
    const float* attn    = (const float*)d_in[1];
    const int*   eli     = (const int*)  d_in[2];
    const float* emb     = (const float*)d_in[3];
    const float* W1      = (const float*)d_in[4];
    const float* b1      = (const float*)d_in[5];
    const float* W2      = (const float*)d_in[6];
    const float* b2      = (const float*)d_in[7];
    float* out = (float*)d_out;
    const int nPred = in_sizes[2] / 2;

    float *pDis, *pH, *pPart;
    __half *pAf, *pBf;
    cudaGetSymbolAddress((void**)&pDis,  g_dis);
    cudaGetSymbolAddress((void**)&pH,    g_H);
    cudaGetSymbolAddress((void**)&pPart, g_part);
    cudaGetSymbolAddress((void**)&pAf,   g_Af);
    cudaGetSymbolAddress((void**)&pBf,   g_Bf);

    // smem: 3 stages x (A 32x72 + B 32x136) halves = 39936 B
    constexpr int TC_SMEM = 3 * (32 * 72 + 32 * 136) * 2;
    cudaFuncSetAttribute(tc_gemm<1, true >, cudaFuncAttributeMaxDynamicSharedMemorySize, TC_SMEM);
    cudaFuncSetAttribute(tc_gemm<2, false>, cudaFuncAttributeMaxDynamicSharedMemorySize, TC_SMEM);

    // 1) convert + deg (fused), then dis
    convert_deg_kernel<<<dim3(8, 128), 256>>>(attn);
    dis_kernel<<<N_NODES / 256, 256>>>();

    // 2) P (fp16 x 2^14) = dis ⊙ (emb[nodeIdx] @ W1)
    simt_gemm<128, 64, 16, 8, 8, true>
        <<<dim3(HID_C / 64, N_NODES / 128), 128>>>(
            emb, E_DIM_C, W1, pBf, pDis, nodeIdx, N_NODES, HID_C, E_DIM_C);

    // 3) H = relu(dis ⊙ (w^T @ P') + b1)   BM=64, no split-K, fused epilogue
    tc_gemm<1, true><<<dim3(HID_C / 128, N_NODES / 64, 1), 64, TC_SMEM>>>(
        pAf, pBf, pH, b1, N_NODES, HID_C, N_NODES);

    // 4) Q (fp16 x 2^14) = dis ⊙ (H @ W2)
    simt_gemm<128, 64, 16, 8, 8, false>
        <<<dim3(OUT_C / 64, N_NODES / 128), 128>>>(
            pH, HID_C, W2, pBf, pDis, nullptr, N_NODES, OUT_C, HID_C);

    // 5) Z partials = w^T @ Q'   BM=64, split-K=2 -> reduce -> fp16 Z
    tc_gemm<2, false><<<dim3(OUT_C / 128, N_NODES / 64, 2), 64, TC_SMEM>>>(
        pAf, pBf, pPart, nullptr, N_NODES, OUT_C, N_NODES);
    reduce_epi_z_kernel<<<(N_NODES * OUT_C / 4 + 255) / 256, 256>>>(pPart, b2);

    // 6) decode (16 lanes per edge)
    decode_kernel<<<(nPred * 16 + 255) / 256, 256>>>(eli, out, nPred);
}

// round 17
// speedup vs baseline: 1.1681x; 1.1681x over previous
#include <cuda_runtime.h>
#include <cuda_fp16.h>
#include <cstdint>

// ---------------------------------------------------------------------------
// Round 16: R14 config (128-thr, BM=128, BN=128, 64x64 warp tile, 2 CTA/SM)
// with BK=64 (half the mainloop iterations/barriers).
//   A (relu(attn)) -> fp16 plane;  B (P/Q) -> fp16 plane scaled 2^14.
//   Z fp16 (L2-resident); 16-lane decode.
// ---------------------------------------------------------------------------

static constexpr int N_NODES = 8192;
static constexpr int E_DIM_C = 256;
static constexpr int HID_C   = 256;
static constexpr int OUT_C   = 128;
static constexpr float B_SCALE     = 16384.0f;       // 2^14
static constexpr float B_INV_SCALE = 1.0f / 16384.0f;

__device__ float   g_degp[128 * N_NODES];
__device__ float   g_dis [N_NODES];
__device__ __half  g_Af  [(size_t)N_NODES * N_NODES];   // 128 MB fp16 relu(attn)
__device__ __half  g_Bf  [N_NODES * HID_C];             // P/Q (scaled fp16)
__device__ float   g_H   [N_NODES * HID_C];
__device__ __half  g_Zh  [N_NODES * OUT_C];             // 2 MB fp16 Z
__device__ float   g_part[4 * N_NODES * OUT_C];         // split-K partials

// ---------------------------------------------------------------------------
__global__ void convert_deg_kernel(const float* __restrict__ attn)
{
    int c4 = blockIdx.x * blockDim.x + threadIdx.x;
    int r0 = blockIdx.y * 64;
    float4 s = make_float4(0.f, 0.f, 0.f, 0.f);
    const float4* a = reinterpret_cast<const float4*>(attn);
    #pragma unroll 4
    for (int r = 0; r < 64; ++r) {
        size_t row = r0 + r;
        float4 v = a[row * (N_NODES / 4) + c4];
        v.x = fmaxf(v.x, 0.f); v.y = fmaxf(v.y, 0.f);
        v.z = fmaxf(v.z, 0.f); v.w = fmaxf(v.w, 0.f);
        s.x += v.x; s.y += v.y; s.z += v.z; s.w += v.w;
        __half2 h0 = __floats2half2_rn(v.x, v.y);
        __half2 h1 = __floats2half2_rn(v.z, v.w);
        uint2 packed;
        packed.x = *reinterpret_cast<uint32_t*>(&h0);
        packed.y = *reinterpret_cast<uint32_t*>(&h1);
        reinterpret_cast<uint2*>(g_Af)[(row * N_NODES) / 4 + c4] = packed;
    }
    reinterpret_cast<float4*>(g_degp)[blockIdx.y * (N_NODES / 4) + c4] = s;
}

__global__ void dis_kernel()
{
    int col = blockIdx.x * blockDim.x + threadIdx.x;
    float s = 0.f;
    #pragma unroll
    for (int r = 0; r < 128; ++r) s += g_degp[(size_t)r * N_NODES + col];
    g_dis[col] = (s > 0.f) ? rsqrtf(s) : 0.f;
}

// ---------------------------------------------------------------------------
__device__ __forceinline__ void ldsm_x4_t(uint32_t& r0, uint32_t& r1,
                                          uint32_t& r2, uint32_t& r3, uint32_t addr)
{
    asm volatile("ldmatrix.sync.aligned.m8n8.x4.trans.shared.b16 {%0,%1,%2,%3}, [%4];"
                 : "=r"(r0), "=r"(r1), "=r"(r2), "=r"(r3) : "r"(addr));
}

__device__ __forceinline__ void mma16816h(float* d, const uint32_t* a, const uint32_t* b)
{
    asm volatile("mma.sync.aligned.m16n8k16.row.col.f32.f16.f16.f32 "
                 "{%0,%1,%2,%3}, {%4,%5,%6,%7}, {%8,%9}, {%0,%1,%2,%3};"
                 : "+f"(d[0]), "+f"(d[1]), "+f"(d[2]), "+f"(d[3])
                 : "r"(a[0]), "r"(a[1]), "r"(a[2]), "r"(a[3]), "r"(b[0]), "r"(b[1]));
}

__device__ __forceinline__ void cpasync16(uint32_t smem, const void* gmem)
{
    asm volatile("cp.async.cg.shared.global [%0], [%1], 16;" :: "r"(smem), "l"(gmem));
}

// ---------------------------------------------------------------------------
// TC GEMM, 64x64 warp tile, 128 threads (2x2 warps), BM=128, BN=128, BK=64.
//   Af: [K, M] fp16, Bf: [K, Ntot] fp16 (pre-scaled). 3-stage cp.async,
//   2 CTAs/SM.
// ---------------------------------------------------------------------------
template<int SPLITK>
__global__ __launch_bounds__(128, 2)
void tc_gemm(const __half* __restrict__ Afg,
             const __half* __restrict__ Bfg,
             float* __restrict__ Cpart, int M, int Ntot, int K)
{
    constexpr int BM = 128, BN = 128, BK = 64;
    constexpr int AP = 136;
    constexpr int BP = BN + 8;
    constexpr int ASTG = BK * AP;
    constexpr int BSTG = BK * BP;
    constexpr int NSTAGE = 3;
    constexpr int NT = 128;
    constexpr int CA = (BK * BM / 8) / NT;        // 8 A-chunks per thread
    constexpr int CB = (BK * BN / 8) / NT;        // 8 B-chunks per thread
    constexpr int BC8 = BN / 8;

    extern __shared__ __half smheap[];
    auto planeA = [&](int s) { return smheap + s * (ASTG + BSTG); };
    auto planeB = [&](int s) { return smheap + s * (ASTG + BSTG) + ASTG; };

    const int tid  = threadIdx.x;
    const int lane = tid & 31;
    const int wid  = tid >> 5;
    const int wm   = (wid >> 1) * 64;             // 2x2 warp grid
    const int wn   = (wid & 1) * 64;
    const int m0   = blockIdx.y * BM;
    const int n0   = blockIdx.x * BN;
    const int Ksp  = K / SPLITK;
    const int kB   = blockIdx.z * Ksp;
    const int KT   = Ksp / BK;

    float acc[4][8][4];
    #pragma unroll
    for (int i = 0; i < 4; ++i)
        #pragma unroll
        for (int j = 0; j < 8; ++j)
            #pragma unroll
            for (int q = 0; q < 4; ++q) acc[i][j][q] = 0.f;

    auto issue = [&](int kt, int s) {
        int kg = kB + kt * BK;
        uint32_t ab = (uint32_t)__cvta_generic_to_shared(planeA(s));
        uint32_t bb = (uint32_t)__cvta_generic_to_shared(planeB(s));
        #pragma unroll
        for (int v = 0; v < CA; ++v) {
            int idx = tid + v * NT;
            int row = idx >> 4;                   // 0..63
            int c16 = idx & 15;
            cpasync16(ab + row * (AP * 2) + c16 * 16,
                      Afg + (size_t)(kg + row) * M + m0 + c16 * 8);
        }
        #pragma unroll
        for (int v = 0; v < CB; ++v) {
            int idx = tid + v * NT;
            int row = idx / BC8;                  // 0..63
            int cc  = idx % BC8;
            cpasync16(bb + row * (BP * 2) + cc * 16,
                      Bfg + (size_t)(kg + row) * Ntot + n0 + cc * 8);
        }
        asm volatile("cp.async.commit_group;");
    };

    const int aRow = (lane & 7) + ((lane >> 4) & 1) * 8;
    const int aCol = wm + ((lane >> 3) & 1) * 8;
    const int bRow = (lane & 7) + ((lane >> 3) & 1) * 8;
    const int bCol = wn + ((lane >> 4) & 1) * 8;

    auto compute = [&](int s) {
        uint32_t ab = (uint32_t)__cvta_generic_to_shared(planeA(s));
        uint32_t bb = (uint32_t)__cvta_generic_to_shared(planeB(s));
        #pragma unroll
        for (int k16 = 0; k16 < BK / 16; ++k16) {
            int k0 = k16 * 16;
            uint32_t bf[8][2];
            #pragma unroll
            for (int p = 0; p < 4; ++p) {
                uint32_t off = ((k0 + bRow) * BP + bCol + p * 16) * 2;
                uint32_t r0, r1, r2, r3;
                ldsm_x4_t(r0, r1, r2, r3, bb + off);
                bf[2 * p][0] = r0; bf[2 * p][1] = r1;
                bf[2 * p + 1][0] = r2; bf[2 * p + 1][1] = r3;
            }
            #pragma unroll
            for (int mi = 0; mi < 4; ++mi) {
                uint32_t af[4];
                uint32_t off = ((k0 + aRow) * AP + aCol + mi * 16) * 2;
                ldsm_x4_t(af[0], af[1], af[2], af[3], ab + off);
                #pragma unroll
                for (int ni = 0; ni < 8; ++ni)
                    mma16816h(acc[mi][ni], af, bf[ni]);
            }
        }
    };

    issue(0, 0);
    if (KT > 1) issue(1, 1);
    if (KT > 2) issue(2, 2);

    for (int kt = 0; kt < KT; ++kt) {
        asm volatile("cp.async.wait_group %0;" :: "n"(NSTAGE - 2));
        __syncthreads();
        compute(kt % NSTAGE);
        __syncthreads();
        if (kt + NSTAGE < KT) {
            issue(kt + NSTAGE, kt % NSTAGE);
        } else if (kt + 1 < KT) {
            asm volatile("cp.async.commit_group;");
        }
    }

    float* Cp = Cpart + (size_t)blockIdx.z * M * Ntot;
    const int rB = m0 + wm + (lane >> 2);
    const int cB = n0 + wn + (lane & 3) * 2;
    #pragma unroll
    for (int mi = 0; mi < 4; ++mi)
        #pragma unroll
        for (int ni = 0; ni < 8; ++ni) {
            int r = rB + mi * 16;
            int c = cB + ni * 8;
            *reinterpret_cast<float2*>(Cp + (size_t)r * Ntot + c) =
                make_float2(acc[mi][ni][0], acc[mi][ni][1]);
            *reinterpret_cast<float2*>(Cp + (size_t)(r + 8) * Ntot + c) =
                make_float2(acc[mi][ni][2], acc[mi][ni][3]);
        }
}

// ---------------------------------------------------------------------------
__global__ void reduce_epi_h_kernel(const float* __restrict__ part,
                                    const float* __restrict__ bias)
{
    int i4 = blockIdx.x * blockDim.x + threadIdx.x;
    constexpr int N = HID_C;
    constexpr int MN4 = N_NODES * N / 4;
    if (i4 >= MN4) return;
    const float4* p = reinterpret_cast<const float4*>(part);
    float4 s = p[i4];
    float4 v = p[i4 + (size_t)MN4];
    s.x += v.x; s.y += v.y; s.z += v.z; s.w += v.w;
    int row = (i4 * 4) / N;
    int col = (i4 * 4) % N;
    float sc = g_dis[row] * B_INV_SCALE;
    float4 bb = *reinterpret_cast<const float4*>(bias + col);
    float4 r;
    r.x = fmaxf(s.x * sc + bb.x, 0.f);
    r.y = fmaxf(s.y * sc + bb.y, 0.f);
    r.z = fmaxf(s.z * sc + bb.z, 0.f);
    r.w = fmaxf(s.w * sc + bb.w, 0.f);
    reinterpret_cast<float4*>(g_H)[i4] = r;
}

__global__ void reduce_epi_z_kernel(const float* __restrict__ part,
                                    const float* __restrict__ bias)
{
    int i4 = blockIdx.x * blockDim.x + threadIdx.x;
    constexpr int N = OUT_C;
    constexpr int MN4 = N_NODES * N / 4;
    if (i4 >= MN4) return;
    const float4* p = reinterpret_cast<const float4*>(part);
    float4 s = p[i4];
    #pragma unroll
    for (int sp = 1; sp < 4; ++sp) {
        float4 v = p[i4 + (size_t)sp * MN4];
        s.x += v.x; s.y += v.y; s.z += v.z; s.w += v.w;
    }
    int row = (i4 * 4) / N;
    int col = (i4 * 4) % N;
    float sc = g_dis[row] * B_INV_SCALE;
    float4 bb = *reinterpret_cast<const float4*>(bias + col);
    __half2 h0 = __floats2half2_rn(s.x * sc + bb.x, s.y * sc + bb.y);
    __half2 h1 = __floats2half2_rn(s.z * sc + bb.z, s.w * sc + bb.w);
    uint2 packed;
    packed.x = *reinterpret_cast<uint32_t*>(&h0);
    packed.y = *reinterpret_cast<uint32_t*>(&h1);
    reinterpret_cast<uint2*>(g_Zh)[i4] = packed;
}

// ---------------------------------------------------------------------------
template<int BM, int BN, int BK, int TM, int TN, bool GATHER_A>
__global__ __launch_bounds__((BM / TM) * (BN / TN))
void simt_gemm(const float* __restrict__ A, int lda,
               const float* __restrict__ B,
               __half* __restrict__ Cf,
               const float* __restrict__ rowScale,
               const int* __restrict__ gatherIdx,
               int M, int N, int K)
{
    constexpr int NT   = (BM / TM) * (BN / TN);
    constexpr int APAD = 4;
    constexpr int AV   = (BM * BK) / (4 * NT);
    constexpr int BV   = (BK * BN) / (4 * NT);

    __shared__ float As[BK][BM + APAD];
    __shared__ float Bs[BK][BN];

    const int tid = threadIdx.x;
    const int tx  = tid % (BN / TN);
    const int ty  = tid / (BN / TN);
    const int m0  = blockIdx.y * BM;
    const int n0  = blockIdx.x * BN;

    float4 areg[AV], breg[BV];
    float acc[TM][TN];
    #pragma unroll
    for (int i = 0; i < TM; ++i)
        #pragma unroll
        for (int j = 0; j < TN; ++j) acc[i][j] = 0.f;

    auto loadA = [&](int k0) {
        #pragma unroll
        for (int v = 0; v < AV; ++v) {
            int idx = tid + v * NT;
            int m  = idx / (BK / 4);
            int kq = idx % (BK / 4);
            int row = GATHER_A ? gatherIdx[m0 + m] : (m0 + m);
            areg[v] = *reinterpret_cast<const float4*>(A + (size_t)row * lda + (k0 + kq * 4));
        }
    };
    auto storeA = [&]() {
        #pragma unroll
        for (int v = 0; v < AV; ++v) {
            int idx = tid + v * NT;
            int m  = idx / (BK / 4);
            int kq = idx % (BK / 4);
            As[kq * 4 + 0][m] = areg[v].x;
            As[kq * 4 + 1][m] = areg[v].y;
            As[kq * 4 + 2][m] = areg[v].z;
            As[kq * 4 + 3][m] = areg[v].w;
        }
    };
    auto loadB = [&](int k0) {
        #pragma unroll
        for (int v = 0; v < BV; ++v) {
            int idx = tid + v * NT;
            int k  = idx / (BN / 4);
            int n4 = idx % (BN / 4);
            breg[v] = *reinterpret_cast<const float4*>(B + (size_t)(k0 + k) * N + (n0 + n4 * 4));
        }
    };
    auto storeB = [&]() {
        #pragma unroll
        for (int v = 0; v < BV; ++v) {
            int idx = tid + v * NT;
            int k  = idx / (BN / 4);
            int n4 = idx % (BN / 4);
            *reinterpret_cast<float4*>(&Bs[k][n4 * 4]) = breg[v];
        }
    };

    loadA(0); loadB(0);
    storeA(); storeB();
    __syncthreads();

    const int KT = K / BK;
    for (int kt = 0; kt < KT; ++kt) {
        if (kt + 1 < KT) { loadA((kt + 1) * BK); loadB((kt + 1) * BK); }
        #pragma unroll
        for (int kk = 0; kk < BK; ++kk) {
            float a[TM], b[TN];
            #pragma unroll
            for (int i = 0; i < TM; i += 4) {
                float4 t = *reinterpret_cast<const float4*>(&As[kk][ty * TM + i]);
                a[i] = t.x; a[i + 1] = t.y; a[i + 2] = t.z; a[i + 3] = t.w;
            }
            #pragma unroll
            for (int j = 0; j < TN; j += 4) {
                float4 t = *reinterpret_cast<const float4*>(&Bs[kk][tx * TN + j]);
                b[j] = t.x; b[j + 1] = t.y; b[j + 2] = t.z; b[j + 3] = t.w;
            }
            #pragma unroll
            for (int i = 0; i < TM; ++i)
                #pragma unroll
                for (int j = 0; j < TN; ++j)
                    acc[i][j] = fmaf(a[i], b[j], acc[i][j]);
        }
        if (kt + 1 < KT) {
            __syncthreads();
            storeA(); storeB();
            __syncthreads();
        }
    }

    #pragma unroll
    for (int i = 0; i < TM; ++i) {
        int row = m0 + ty * TM + i;
        float sc = rowScale[row] * B_SCALE;
        #pragma unroll
        for (int j = 0; j < TN; j += 4) {
            int col = n0 + tx * TN + j;
            __half h[4];
            h[0] = __float2half_rn(acc[i][j + 0] * sc);
            h[1] = __float2half_rn(acc[i][j + 1] * sc);
            h[2] = __float2half_rn(acc[i][j + 2] * sc);
            h[3] = __float2half_rn(acc[i][j + 3] * sc);
            reinterpret_cast<uint2*>(Cf)[((size_t)row * N + col) / 4] =
                *reinterpret_cast<uint2*>(h);
        }
    }
}

// ---------------------------------------------------------------------------
// decode: 16 lanes per edge, uint4 loads of fp16 Z.
// ---------------------------------------------------------------------------
__global__ __launch_bounds__(256)
void decode_kernel(const int* __restrict__ eli,
                   float* __restrict__ out, int nPred)
{
    int g = blockIdx.x * blockDim.x + threadIdx.x;
    int e = g >> 4;
    int l16 = threadIdx.x & 15;
    if (e >= nPred) return;
    int s = __ldg(eli + e);
    int d = __ldg(eli + nPred + e);
    const uint4* zs = reinterpret_cast<const uint4*>(g_Zh + (size_t)s * OUT_C);
    const uint4* zd = reinterpret_cast<const uint4*>(g_Zh + (size_t)d * OUT_C);
    uint4 ar = __ldg(zs + l16);
    uint4 br = __ldg(zd + l16);
    float dot = 0.f;
    const uint32_t* au = &ar.x;
    const uint32_t* bu = &br.x;
    #pragma unroll
    for (int q = 0; q < 4; ++q) {
        __half2 ah = *reinterpret_cast<const __half2*>(&au[q]);
        __half2 bh = *reinterpret_cast<const __half2*>(&bu[q]);
        float2 af = __half22float2(ah);
        float2 bf = __half22float2(bh);
        dot += af.x * bf.x + af.y * bf.y;
    }
    #pragma unroll
    for (int o = 8; o; o >>= 1) dot += __shfl_xor_sync(0xffffffffu, dot, o);
    if (l16 == 0) out[e] = dot;
}

// ---------------------------------------------------------------------------
extern "C" void kernel_launch(void* const* d_in, const int* in_sizes, int n_in,
                              void* d_out, int out_size)
{
    const int*   nodeIdx = (const int*)  d_in[0];
    const float* attn    = (const float*)d_in[1];
    const int*   eli     = (const int*)  d_in[2];
    const float* emb     = (const float*)d_in[3];
    const float* W1      = (const float*)d_in[4];
    const float* b1      = (const float*)d_in[5];
    const float* W2      = (const float*)d_in[6];
    const float* b2      = (const float*)d_in[7];
    float* out = (float*)d_out;
    const int nPred = in_sizes[2] / 2;

    float *pDis, *pH, *pPart;
    __half *pAf, *pBf;
    cudaGetSymbolAddress((void**)&pDis,  g_dis);
    cudaGetSymbolAddress((void**)&pH,    g_H);
    cudaGetSymbolAddress((void**)&pPart, g_part);
    cudaGetSymbolAddress((void**)&pAf,   g_Af);
    cudaGetSymbolAddress((void**)&pBf,   g_Bf);

    // smem: 3 stages x (A 64x136 + B 64x136) halves = 104448 B
    constexpr int TC_SMEM = 3 * (64 * 136 + 64 * 136) * 2;
    cudaFuncSetAttribute(tc_gemm<2>, cudaFuncAttributeMaxDynamicSharedMemorySize, TC_SMEM);
    cudaFuncSetAttribute(tc_gemm<4>, cudaFuncAttributeMaxDynamicSharedMemorySize, TC_SMEM);

    // 1) convert + deg (fused), then dis
    convert_deg_kernel<<<dim3(8, 128), 256>>>(attn);
    dis_kernel<<<N_NODES / 256, 256>>>();

    // 2) P (fp16 x 2^14) = dis ⊙ (emb[nodeIdx] @ W1)
    simt_gemm<128, 64, 16, 8, 8, true>
        <<<dim3(HID_C / 64, N_NODES / 128), 128>>>(
            emb, E_DIM_C, W1, pBf, pDis, nodeIdx, N_NODES, HID_C, E_DIM_C);

    // 3) H partials = w^T @ P'   split-K=2, 128 thr, BN=128, BK=64
    tc_gemm<2><<<dim3(HID_C / 128, N_NODES / 128, 2), 128, TC_SMEM>>>(
        pAf, pBf, pPart, N_NODES, HID_C, N_NODES);
    reduce_epi_h_kernel<<<(N_NODES * HID_C / 4 + 255) / 256, 256>>>(pPart, b1);

    // 4) Q (fp16 x 2^14) = dis ⊙ (H @ W2)
    simt_gemm<128, 64, 16, 8, 8, false>
        <<<dim3(OUT_C / 64, N_NODES / 128), 128>>>(
            pH, HID_C, W2, pBf, pDis, nullptr, N_NODES, OUT_C, HID_C);

    // 5) Z partials = w^T @ Q'   split-K=4, same shape
    tc_gemm<4><<<dim3(OUT_C / 128, N_NODES / 128, 4), 128, TC_SMEM>>>(
        pAf, pBf, pPart, N_NODES, OUT_C, N_NODES);
    reduce_epi_z_kernel<<<(N_NODES * OUT_C / 4 + 255) / 256, 256>>>(pPart, b2);

    // 6) decode (16 lanes per edge)
    decode_kernel<<<(nPred * 16 + 255) / 256, 256>>>(eli, out, nPred);
}